// round 13
// baseline (speedup 1.0000x reference)
#include <cuda_runtime.h>
#include <math.h>

#define D_ 128
#define NB_ 20
#define EMAX 200000
#define FULLMASK 0xffffffffu

typedef unsigned long long u64;

// ---------------- f32x2 packed-math helpers (FFMA2: ptxas won't auto-fuse) ----------------
__device__ __forceinline__ u64 pack2(float lo, float hi) {
    u64 r; asm("mov.b64 %0, {%1, %2};" : "=l"(r) : "f"(lo), "f"(hi)); return r;
}
__device__ __forceinline__ void unpack2(u64 v, float& lo, float& hi) {
    asm("mov.b64 {%0, %1}, %2;" : "=f"(lo), "=f"(hi) : "l"(v));
}
__device__ __forceinline__ void ffma2(u64& d, u64 a, u64 b) {
    asm("fma.rn.f32x2 %0, %1, %2, %0;" : "+l"(d) : "l"(a), "l"(b));
}
__device__ __forceinline__ u64 fadd2(u64 a, u64 b) {
    u64 r; asm("add.rn.f32x2 %0, %1, %2;" : "=l"(r) : "l"(a), "l"(b)); return r;
}

// ---------------- scratch (device globals; no allocation allowed) ----------------
__device__ float  g_P[(size_t)EMAX * D_];    // edge_attr @ W1[0:128]
__device__ float  g_Q[(size_t)EMAX * D_];    // edge_attr @ W1[128:256]
__device__ int    g_cnt[EMAX];               // triplet count per e_ij (for b2 term)
__device__ float4 g_geo[EMAX];               // (v/len, len) per edge
__device__ float  g_Wc[D_ * D_];             // W2 @ Wu
__device__ float  g_bcu[D_];                 // b2 @ Wu
__device__ float  g_A2c[NB_ * D_];           // A2 @ W1c   (W1c = W1 rows 256..275)
__device__ float  g_b1p[D_];                 // b1 + ab2 @ W1c

// ---------------- zero scratch (S lives in d_out) ----------------
__global__ void zero_kernel(float* __restrict__ S, int E) {
    const int stride = gridDim.x * blockDim.x;
    const int n4 = E * (D_ / 4);
    float4 z = make_float4(0.f, 0.f, 0.f, 0.f);
    for (int i = blockIdx.x * blockDim.x + threadIdx.x; i < n4; i += stride)
        reinterpret_cast<float4*>(S)[i] = z;
    for (int i = blockIdx.x * blockDim.x + threadIdx.x; i < E; i += stride)
        g_cnt[i] = 0;
}

// ---------------- per-edge geometry: normalized vector + clamped length ----------------
__global__ void geo_kernel(const float* __restrict__ ev, int E) {
    const int e = blockIdx.x * blockDim.x + threadIdx.x;
    if (e >= E) return;
    const float x = ev[3 * e + 0], y = ev[3 * e + 1], z = ev[3 * e + 2];
    const float len = fmaxf(sqrtf(x * x + y * y + z * z), 1e-6f);
    const float inv = 1.f / len;
    g_geo[e] = make_float4(x * inv, y * inv, z * inv, len);
}

// ---------------- tiny precompute: Wc, bcu, A2c, b1p ----------------
__global__ void prep_kernel(const float* __restrict__ W2, const float* __restrict__ Wu,
                            const float* __restrict__ b2, const float* __restrict__ A2,
                            const float* __restrict__ W1, const float* __restrict__ ab2,
                            const float* __restrict__ b1) {
    const int c = threadIdx.x;           // 0..127
    const int blk = blockIdx.x;
    if (blk < 128) {
        float acc = 0.f;
        #pragma unroll 4
        for (int j = 0; j < 128; j++) acc = fmaf(W2[blk * 128 + j], Wu[j * 128 + c], acc);
        g_Wc[blk * 128 + c] = acc;
    } else if (blk < 128 + NB_) {
        const int k = blk - 128;
        float acc = 0.f;
        #pragma unroll
        for (int j = 0; j < NB_; j++) acc = fmaf(A2[k * NB_ + j], W1[(256 + j) * 128 + c], acc);
        g_A2c[k * 128 + c] = acc;
    } else {
        float acc = 0.f;
        #pragma unroll 4
        for (int j = 0; j < 128; j++) acc = fmaf(b2[j], Wu[j * 128 + c], acc);
        g_bcu[c] = acc;
        float acc2 = b1[c];
        #pragma unroll
        for (int j = 0; j < NB_; j++) acc2 = fmaf(ab2[j], W1[(256 + j) * 128 + c], acc2);
        g_b1p[c] = acc2;
    }
}

// ---------------- fp32 tiled GEMM: C[M x 128] = A[M x 128] @ B[128 x 128] (+epilogue) ----------------
// 128x128 block tile, 256 threads, 8x8 per-thread micro-tile via FFMA2, double-buffered smem.
// In-place safe for C == A: block b reads only A rows [b*128, b*128+128), all consumed
// into smem/regs in the mainloop before the epilogue writes those same rows.
__global__ __launch_bounds__(256, 2)
void sgemm128(const float* A, const float* __restrict__ B,
              float* C, int M,
              const float* __restrict__ bias,   // nullable, per-column
              const int* __restrict__ cnt,      // nullable, per-row
              const float* __restrict__ cbias)  // per-column, used with cnt
{
    __shared__ __align__(16) float As[2][8][128];   // [k][m] (transposed A tile)
    __shared__ __align__(16) float Bs[2][8][128];   // [k][n]

    const int tid = threadIdx.x;
    const int row0 = blockIdx.x * 128;
    const int tx = tid & 15;          // col group 0..15
    const int ty = tid >> 4;          // row group 0..15

    const int a_row = tid >> 1;       // 0..127
    const int a_k   = (tid & 1) << 2; // 0 or 4
    const int b_row = tid >> 5;       // 0..7
    const int b_col = (tid & 31) << 2;

    const bool a_valid = (row0 + a_row) < M;
    const float* Ap = A + (size_t)(row0 + a_row) * 128 + a_k;
    const float* Bp = B + b_row * 128 + b_col;

    float4 a4 = a_valid ? *reinterpret_cast<const float4*>(Ap)
                        : make_float4(0.f, 0.f, 0.f, 0.f);
    float4 b4 = *reinterpret_cast<const float4*>(Bp);
    As[0][a_k + 0][a_row] = a4.x;
    As[0][a_k + 1][a_row] = a4.y;
    As[0][a_k + 2][a_row] = a4.z;
    As[0][a_k + 3][a_row] = a4.w;
    *reinterpret_cast<float4*>(&Bs[0][b_row][b_col]) = b4;
    __syncthreads();

    u64 accp[8][4];
    const u64 z2 = pack2(0.f, 0.f);
    #pragma unroll
    for (int i = 0; i < 8; i++)
        #pragma unroll
        for (int j = 0; j < 4; j++) accp[i][j] = z2;

    int buf = 0;
    #pragma unroll 1
    for (int kk = 8; kk <= 128; kk += 8) {
        const bool has_next = (kk < 128);
        float4 na4, nb4;
        if (has_next) {
            na4 = a_valid ? *reinterpret_cast<const float4*>(Ap + kk)
                          : make_float4(0.f, 0.f, 0.f, 0.f);
            nb4 = *reinterpret_cast<const float4*>(Bp + kk * 128);
        }
        #pragma unroll
        for (int k = 0; k < 8; k++) {
            float ar[8];
            *reinterpret_cast<float4*>(&ar[0]) = *reinterpret_cast<const float4*>(&As[buf][k][ty * 8]);
            *reinterpret_cast<float4*>(&ar[4]) = *reinterpret_cast<const float4*>(&As[buf][k][ty * 8 + 4]);
            const ulonglong2 b01 = *reinterpret_cast<const ulonglong2*>(&Bs[buf][k][tx * 8]);
            const ulonglong2 b23 = *reinterpret_cast<const ulonglong2*>(&Bs[buf][k][tx * 8 + 4]);
            u64 brp[4];
            brp[0] = b01.x; brp[1] = b01.y; brp[2] = b23.x; brp[3] = b23.y;
            #pragma unroll
            for (int i = 0; i < 8; i++) {
                const u64 aa = pack2(ar[i], ar[i]);
                ffma2(accp[i][0], aa, brp[0]);
                ffma2(accp[i][1], aa, brp[1]);
                ffma2(accp[i][2], aa, brp[2]);
                ffma2(accp[i][3], aa, brp[3]);
            }
        }
        if (has_next) {
            const int nb = buf ^ 1;
            As[nb][a_k + 0][a_row] = na4.x;
            As[nb][a_k + 1][a_row] = na4.y;
            As[nb][a_k + 2][a_row] = na4.z;
            As[nb][a_k + 3][a_row] = na4.w;
            *reinterpret_cast<float4*>(&Bs[nb][b_row][b_col]) = nb4;
            __syncthreads();
            buf = nb;
        }
    }

    // epilogue
    float4 bias_lo = make_float4(0.f, 0.f, 0.f, 0.f), bias_hi = bias_lo;
    float4 cb_lo = bias_lo, cb_hi = bias_lo;
    if (bias) {
        bias_lo = *reinterpret_cast<const float4*>(bias + tx * 8);
        bias_hi = *reinterpret_cast<const float4*>(bias + tx * 8 + 4);
    }
    if (cnt) {
        cb_lo = *reinterpret_cast<const float4*>(cbias + tx * 8);
        cb_hi = *reinterpret_cast<const float4*>(cbias + tx * 8 + 4);
    }
    #pragma unroll
    for (int i = 0; i < 8; i++) {
        const int r = row0 + ty * 8 + i;
        if (r >= M) continue;
        const float cm = cnt ? (float)cnt[r] : 0.f;
        float c0, c1, c2, c3, c4, c5, c6, c7;
        unpack2(accp[i][0], c0, c1);
        unpack2(accp[i][1], c2, c3);
        unpack2(accp[i][2], c4, c5);
        unpack2(accp[i][3], c6, c7);
        float4 o1, o2;
        o1.x = c0 + bias_lo.x + cm * cb_lo.x;
        o1.y = c1 + bias_lo.y + cm * cb_lo.y;
        o1.z = c2 + bias_lo.z + cm * cb_lo.z;
        o1.w = c3 + bias_lo.w + cm * cb_lo.w;
        o2.x = c4 + bias_hi.x + cm * cb_hi.x;
        o2.y = c5 + bias_hi.y + cm * cb_hi.y;
        o2.z = c6 + bias_hi.z + cm * cb_hi.z;
        o2.w = c7 + bias_hi.w + cm * cb_hi.w;
        float* Cp = C + (size_t)r * 128 + tx * 8;
        *reinterpret_cast<float4*>(Cp) = o1;
        *reinterpret_cast<float4*>(Cp + 4) = o2;
    }
}

// ---------------- per-triplet kernel: A2c REGISTER-resident + depth-2 ring ----------------
// MIO analysis: the previous smem version spent ~285us re-loading the SAME A2c
// through the crossbar (20 LDS.128/task = 80 crossbar-cyc/task). Registers load it
// once. Budget: wk 80 + ring 36 + consts/temps ~36 = ~152 regs -> no spills at the
// 170-reg cap of __launch_bounds__(128,3); 12 warps/SM, depth-2 pipeline for gathers.
__device__ __forceinline__ float silu_f(float x) {
    return x / (1.f + __expf(-x));
}

__global__ __launch_bounds__(128, 3)
void triplet_kernel(const int* __restrict__ tbe,
                    const float* __restrict__ A1, const float* __restrict__ ab1,
                    float* __restrict__ S, int T) {
    const int lane = threadIdx.x & 31;
    const int wid  = threadIdx.x >> 5;
    const int step = gridDim.x * 4;
    int t = blockIdx.x * 4 + wid;

    // A2c register-resident: lane owns cols [lane*4, lane*4+4) as 2 u64, loaded ONCE
    u64 wk0[NB_], wk1[NB_];
    const ulonglong2* A2c4 = reinterpret_cast<const ulonglong2*>(g_A2c);
    #pragma unroll
    for (int k = 0; k < NB_; k++) {
        const ulonglong2 w = A2c4[k * (D_ / 4) + lane];
        wk0[k] = w.x;
        wk1[k] = w.y;
    }
    const ulonglong2 bq = reinterpret_cast<const ulonglong2*>(g_b1p)[lane];
    const u64 bp0 = bq.x, bp1 = bq.y;

    // per-lane angle-MLP constants (lanes 0..19 active)
    float a10 = 0.f, a11 = 0.f, a12 = 0.f, rab1 = 0.f;
    if (lane < NB_) {
        a10 = A1[0 * NB_ + lane];
        a11 = A1[1 * NB_ + lane];
        a12 = A1[2 * NB_ + lane];
        rab1 = ab1[lane];
    }

    if (t >= T) return;
    const int2* tbe2 = reinterpret_cast<const int2*>(tbe);
    const int Tm1 = T - 1;

    // depth-2 ring: slot parity = task parity; unroll 2 so indices are compile-time
    int2       e2s[2];
    float4     gijs[2], giks[2];
    ulonglong2 pvs[2], qvs[2];

    // prologue: indices for t and t+step; gathers for slot 0 (task t)
    e2s[0] = tbe2[t];
    e2s[1] = tbe2[min(t + step, Tm1)];
    gijs[0] = g_geo[e2s[0].x];
    giks[0] = g_geo[e2s[0].y];
    pvs[0] = reinterpret_cast<const ulonglong2*>(g_P + (size_t)e2s[0].x * D_)[lane];
    qvs[0] = reinterpret_cast<const ulonglong2*>(g_Q + (size_t)e2s[0].y * D_)[lane];
    int tpi = t + 2 * step;   // next index to prefetch

    #pragma unroll 1
    while (t < T) {
        #pragma unroll
        for (int s = 0; s < 2; s++) {
            if (t >= T) break;
            const int so = s ^ 1;

            // issue gathers for task t+step from slot so (its e2 prefetched last body)
            {
                const int2 e = e2s[so];
                gijs[so] = g_geo[e.x];
                giks[so] = g_geo[e.y];
                pvs[so] = reinterpret_cast<const ulonglong2*>(g_P + (size_t)e.x * D_)[lane];
                qvs[so] = reinterpret_cast<const ulonglong2*>(g_Q + (size_t)e.y * D_)[lane];
            }

            // ---- compute task t from slot s ----
            const int eij = e2s[s].x;
            const float4 gij = gijs[s], gik = giks[s];
            float cosv = gij.x * gik.x + gij.y * gik.y + gij.z * gik.z;
            cosv = fminf(fmaxf(cosv, -1.f), 1.f);
            const float zz = fmaf(gij.w, a10, fmaf(gik.w, a11, fmaf(cosv, a12, rab1)));
            const float h1 = silu_f(zz);   // lane j holds h1[j] (j<20)

            u64 acc0 = fadd2(fadd2(pvs[s].x, qvs[s].x), bp0);
            u64 acc1 = fadd2(fadd2(pvs[s].y, qvs[s].y), bp1);

            #pragma unroll
            for (int k = 0; k < NB_; k++) {
                const float hk = __shfl_sync(FULLMASK, h1, k);
                const u64 hh = pack2(hk, hk);
                ffma2(acc0, hh, wk0[k]);
                ffma2(acc1, hh, wk1[k]);
            }

            float m0, m1, m2, m3;
            unpack2(acc0, m0, m1);
            unpack2(acc1, m2, m3);
            m0 = silu_f(m0);
            m1 = silu_f(m1);
            m2 = silu_f(m2);
            m3 = silu_f(m3);

            float* dst = S + (size_t)eij * D_ + lane * 4;
            asm volatile("red.global.add.v4.f32 [%0], {%1, %2, %3, %4};"
                         :: "l"(dst), "f"(m0), "f"(m1), "f"(m2), "f"(m3) : "memory");
            if (lane == 0)
                asm volatile("red.global.add.u32 [%0], %1;"
                             :: "l"(&g_cnt[eij]), "r"(1) : "memory");

            // prefetch indices for task t+2*step into the now-free slot s
            e2s[s] = tbe2[min(tpi, Tm1)];
            tpi += step;

            t += step;
        }
    }
}

// ---------------- launch ----------------
extern "C" void kernel_launch(void* const* d_in, const int* in_sizes, int n_in,
                              void* d_out, int out_size) {
    const float* edge_attr = (const float*)d_in[0];
    // d_in[1] = three_body_indices (unused by the math)
    const int*   tbe       = (const int*)d_in[2];
    const float* ev        = (const float*)d_in[3];
    const float* A1        = (const float*)d_in[4];
    const float* ab1       = (const float*)d_in[5];
    const float* A2        = (const float*)d_in[6];
    const float* ab2       = (const float*)d_in[7];
    const float* W1        = (const float*)d_in[8];
    const float* b1        = (const float*)d_in[9];
    const float* W2        = (const float*)d_in[10];
    const float* b2        = (const float*)d_in[11];
    const float* Wu        = (const float*)d_in[12];
    const float* bu        = (const float*)d_in[13];
    float* out = (float*)d_out;

    const int E = in_sizes[0] / D_;
    const int T = in_sizes[2] / 2;

    void *pP, *pQ, *pcnt, *pWc, *pbcu;
    cudaGetSymbolAddress(&pP, g_P);
    cudaGetSymbolAddress(&pQ, g_Q);
    cudaGetSymbolAddress(&pcnt, g_cnt);
    cudaGetSymbolAddress(&pWc, g_Wc);
    cudaGetSymbolAddress(&pbcu, g_bcu);

    // S (segment sum of silu(pre)) lives in d_out; final GEMM is in-place.
    zero_kernel<<<1184, 256>>>(out, E);
    geo_kernel<<<(E + 255) / 256, 256>>>(ev, E);
    prep_kernel<<<128 + NB_ + 1, 128>>>(W2, Wu, b2, A2, W1, ab2, b1);

    const int gb = (E + 127) / 128;
    sgemm128<<<gb, 256>>>(edge_attr, W1, (float*)pP, E, nullptr, nullptr, nullptr);
    sgemm128<<<gb, 256>>>(edge_attr, W1 + 128 * 128, (float*)pQ, E, nullptr, nullptr, nullptr);

    triplet_kernel<<<888, 128>>>(tbe, A1, ab1, out, T);

    sgemm128<<<gb, 256>>>(out, (const float*)pWc, out, E,
                          bu, (const int*)pcnt, (const float*)pbcu);
}

// round 16
// speedup vs baseline: 1.2570x; 1.2570x over previous
#include <cuda_runtime.h>
#include <math.h>

#define D_ 128
#define NB_ 20
#define BT_ 128
#define EMAX 200000
#define FULLMASK 0xffffffffu

typedef unsigned long long u64;

// ---------------- f32x2 packed-math helpers (FFMA2: ptxas won't auto-fuse) ----------------
__device__ __forceinline__ u64 pack2(float lo, float hi) {
    u64 r; asm("mov.b64 %0, {%1, %2};" : "=l"(r) : "f"(lo), "f"(hi)); return r;
}
__device__ __forceinline__ void unpack2(u64 v, float& lo, float& hi) {
    asm("mov.b64 {%0, %1}, %2;" : "=f"(lo), "=f"(hi) : "l"(v));
}
__device__ __forceinline__ void ffma2(u64& d, u64 a, u64 b) {
    asm("fma.rn.f32x2 %0, %1, %2, %0;" : "+l"(d) : "l"(a), "l"(b));
}
__device__ __forceinline__ u64 fadd2(u64 a, u64 b) {
    u64 r; asm("add.rn.f32x2 %0, %1, %2;" : "=l"(r) : "l"(a), "l"(b)); return r;
}

// ---------------- scratch (device globals; no allocation allowed) ----------------
__device__ float  g_P[(size_t)EMAX * D_];    // edge_attr @ W1[0:128]
__device__ float  g_Q[(size_t)EMAX * D_];    // edge_attr @ W1[128:256]
__device__ int    g_cnt[EMAX];               // triplet count per e_ij (for b2 term)
__device__ float4 g_geo[EMAX];               // (v/len, len) per edge
__device__ float  g_Wc[D_ * D_];             // W2 @ Wu
__device__ float  g_bcu[D_];                 // b2 @ Wu
__device__ float  g_A2c[NB_ * D_];           // A2 @ W1c   (W1c = W1 rows 256..275)
__device__ float  g_b1p[D_];                 // b1 + ab2 @ W1c

// ---------------- zero scratch (S lives in d_out) ----------------
__global__ void zero_kernel(float* __restrict__ S, int E) {
    const int stride = gridDim.x * blockDim.x;
    const int n4 = E * (D_ / 4);
    float4 z = make_float4(0.f, 0.f, 0.f, 0.f);
    for (int i = blockIdx.x * blockDim.x + threadIdx.x; i < n4; i += stride)
        reinterpret_cast<float4*>(S)[i] = z;
    for (int i = blockIdx.x * blockDim.x + threadIdx.x; i < E; i += stride)
        g_cnt[i] = 0;
}

// ---------------- per-edge geometry: normalized vector + clamped length ----------------
__global__ void geo_kernel(const float* __restrict__ ev, int E) {
    const int e = blockIdx.x * blockDim.x + threadIdx.x;
    if (e >= E) return;
    const float x = ev[3 * e + 0], y = ev[3 * e + 1], z = ev[3 * e + 2];
    const float len = fmaxf(sqrtf(x * x + y * y + z * z), 1e-6f);
    const float inv = 1.f / len;
    g_geo[e] = make_float4(x * inv, y * inv, z * inv, len);
}

// ---------------- tiny precompute: Wc, bcu, A2c, b1p ----------------
__global__ void prep_kernel(const float* __restrict__ W2, const float* __restrict__ Wu,
                            const float* __restrict__ b2, const float* __restrict__ A2,
                            const float* __restrict__ W1, const float* __restrict__ ab2,
                            const float* __restrict__ b1) {
    const int c = threadIdx.x;           // 0..127
    const int blk = blockIdx.x;
    if (blk < 128) {
        float acc = 0.f;
        #pragma unroll 4
        for (int j = 0; j < 128; j++) acc = fmaf(W2[blk * 128 + j], Wu[j * 128 + c], acc);
        g_Wc[blk * 128 + c] = acc;
    } else if (blk < 128 + NB_) {
        const int k = blk - 128;
        float acc = 0.f;
        #pragma unroll
        for (int j = 0; j < NB_; j++) acc = fmaf(A2[k * NB_ + j], W1[(256 + j) * 128 + c], acc);
        g_A2c[k * 128 + c] = acc;
    } else {
        float acc = 0.f;
        #pragma unroll 4
        for (int j = 0; j < 128; j++) acc = fmaf(b2[j], Wu[j * 128 + c], acc);
        g_bcu[c] = acc;
        float acc2 = b1[c];
        #pragma unroll
        for (int j = 0; j < NB_; j++) acc2 = fmaf(ab2[j], W1[(256 + j) * 128 + c], acc2);
        g_b1p[c] = acc2;
    }
}

// ---------------- fp32 tiled GEMM: C[M x 128] = A[M x 128] @ B[128 x 128] (+epilogue) ----------------
// 128x128 block tile, 256 threads, 8x8 per-thread micro-tile via FFMA2, double-buffered smem.
// In-place safe for C == A: block b reads only A rows [b*128, b*128+128), all consumed
// into smem/regs in the mainloop before the epilogue writes those same rows.
__global__ __launch_bounds__(256, 2)
void sgemm128(const float* A, const float* __restrict__ B,
              float* C, int M,
              const float* __restrict__ bias,   // nullable, per-column
              const int* __restrict__ cnt,      // nullable, per-row
              const float* __restrict__ cbias)  // per-column, used with cnt
{
    __shared__ __align__(16) float As[2][8][128];   // [k][m] (transposed A tile)
    __shared__ __align__(16) float Bs[2][8][128];   // [k][n]

    const int tid = threadIdx.x;
    const int row0 = blockIdx.x * 128;
    const int tx = tid & 15;          // col group 0..15
    const int ty = tid >> 4;          // row group 0..15

    const int a_row = tid >> 1;       // 0..127
    const int a_k   = (tid & 1) << 2; // 0 or 4
    const int b_row = tid >> 5;       // 0..7
    const int b_col = (tid & 31) << 2;

    const bool a_valid = (row0 + a_row) < M;
    const float* Ap = A + (size_t)(row0 + a_row) * 128 + a_k;
    const float* Bp = B + b_row * 128 + b_col;

    float4 a4 = a_valid ? *reinterpret_cast<const float4*>(Ap)
                        : make_float4(0.f, 0.f, 0.f, 0.f);
    float4 b4 = *reinterpret_cast<const float4*>(Bp);
    As[0][a_k + 0][a_row] = a4.x;
    As[0][a_k + 1][a_row] = a4.y;
    As[0][a_k + 2][a_row] = a4.z;
    As[0][a_k + 3][a_row] = a4.w;
    *reinterpret_cast<float4*>(&Bs[0][b_row][b_col]) = b4;
    __syncthreads();

    u64 accp[8][4];
    const u64 z2 = pack2(0.f, 0.f);
    #pragma unroll
    for (int i = 0; i < 8; i++)
        #pragma unroll
        for (int j = 0; j < 4; j++) accp[i][j] = z2;

    int buf = 0;
    #pragma unroll 1
    for (int kk = 8; kk <= 128; kk += 8) {
        const bool has_next = (kk < 128);
        float4 na4, nb4;
        if (has_next) {
            na4 = a_valid ? *reinterpret_cast<const float4*>(Ap + kk)
                          : make_float4(0.f, 0.f, 0.f, 0.f);
            nb4 = *reinterpret_cast<const float4*>(Bp + kk * 128);
        }
        #pragma unroll
        for (int k = 0; k < 8; k++) {
            float ar[8];
            *reinterpret_cast<float4*>(&ar[0]) = *reinterpret_cast<const float4*>(&As[buf][k][ty * 8]);
            *reinterpret_cast<float4*>(&ar[4]) = *reinterpret_cast<const float4*>(&As[buf][k][ty * 8 + 4]);
            const ulonglong2 b01 = *reinterpret_cast<const ulonglong2*>(&Bs[buf][k][tx * 8]);
            const ulonglong2 b23 = *reinterpret_cast<const ulonglong2*>(&Bs[buf][k][tx * 8 + 4]);
            u64 brp[4];
            brp[0] = b01.x; brp[1] = b01.y; brp[2] = b23.x; brp[3] = b23.y;
            #pragma unroll
            for (int i = 0; i < 8; i++) {
                const u64 aa = pack2(ar[i], ar[i]);
                ffma2(accp[i][0], aa, brp[0]);
                ffma2(accp[i][1], aa, brp[1]);
                ffma2(accp[i][2], aa, brp[2]);
                ffma2(accp[i][3], aa, brp[3]);
            }
        }
        if (has_next) {
            const int nb = buf ^ 1;
            As[nb][a_k + 0][a_row] = na4.x;
            As[nb][a_k + 1][a_row] = na4.y;
            As[nb][a_k + 2][a_row] = na4.z;
            As[nb][a_k + 3][a_row] = na4.w;
            *reinterpret_cast<float4*>(&Bs[nb][b_row][b_col]) = nb4;
            __syncthreads();
            buf = nb;
        }
    }

    // epilogue
    float4 bias_lo = make_float4(0.f, 0.f, 0.f, 0.f), bias_hi = bias_lo;
    float4 cb_lo = bias_lo, cb_hi = bias_lo;
    if (bias) {
        bias_lo = *reinterpret_cast<const float4*>(bias + tx * 8);
        bias_hi = *reinterpret_cast<const float4*>(bias + tx * 8 + 4);
    }
    if (cnt) {
        cb_lo = *reinterpret_cast<const float4*>(cbias + tx * 8);
        cb_hi = *reinterpret_cast<const float4*>(cbias + tx * 8 + 4);
    }
    #pragma unroll
    for (int i = 0; i < 8; i++) {
        const int r = row0 + ty * 8 + i;
        if (r >= M) continue;
        const float cm = cnt ? (float)cnt[r] : 0.f;
        float c0, c1, c2, c3, c4, c5, c6, c7;
        unpack2(accp[i][0], c0, c1);
        unpack2(accp[i][1], c2, c3);
        unpack2(accp[i][2], c4, c5);
        unpack2(accp[i][3], c6, c7);
        float4 o1, o2;
        o1.x = c0 + bias_lo.x + cm * cb_lo.x;
        o1.y = c1 + bias_lo.y + cm * cb_lo.y;
        o1.z = c2 + bias_lo.z + cm * cb_lo.z;
        o1.w = c3 + bias_lo.w + cm * cb_lo.w;
        o2.x = c4 + bias_hi.x + cm * cb_hi.x;
        o2.y = c5 + bias_hi.y + cm * cb_hi.y;
        o2.z = c6 + bias_hi.z + cm * cb_hi.z;
        o2.w = c7 + bias_hi.w + cm * cb_hi.w;
        float* Cp = C + (size_t)r * 128 + tx * 8;
        *reinterpret_cast<float4*>(Cp) = o1;
        *reinterpret_cast<float4*>(Cp + 4) = o2;
    }
}

// ---------------- batched triplet kernel: 128 triplets/CTA, contraction as GEMM ----------------
// Phase 1 (threads 0..127): one thread per triplet -> H[20 x 128] (transposed) in smem.
// Phase 2 (256 threads, 8x8 micro-tile): pre[128 x 128] = H^T @ A2c + b1p, then per-row
// gather P[e_ij]/Q[e_ik] (16 threads x 32B = full coalesced 512B row), add, silu, red.v4.
// Eliminates all per-task SHFLs and cuts smem crossbar traffic ~4x vs the warp-per-task form.
__device__ __forceinline__ float silu_f(float x) {
    return x / (1.f + __expf(-x));
}

__global__ __launch_bounds__(256, 2)
void triplet_batch_kernel(const int* __restrict__ tbe,
                          const float* __restrict__ A1, const float* __restrict__ ab1,
                          float* __restrict__ S, int T) {
    __shared__ __align__(16) float sH[NB_][BT_];     // H transposed: [k][triplet]
    __shared__ __align__(16) float sA2c[NB_][D_];    // 20 x 128
    __shared__ __align__(16) float sb1p[D_];
    __shared__ float sA1[3][NB_];
    __shared__ float sab1[NB_];
    __shared__ int   sei[BT_], sek[BT_];

    const int tid = threadIdx.x;

    // ---- load constants ----
    for (int i = tid * 4; i < NB_ * D_; i += 256 * 4)
        *reinterpret_cast<float4*>(&sA2c[0][0] + i) = *reinterpret_cast<const float4*>(&g_A2c[i]);
    if (tid < D_) sb1p[tid] = g_b1p[tid];
    if (tid < 3 * NB_) sA1[0][tid] = A1[tid];        // row-major (3,20) flat
    if (tid >= 64 && tid < 64 + NB_) sab1[tid - 64] = ab1[tid - 64];
    __syncthreads();

    // ---- phase 1: build H for this block's 128 triplets ----
    const int t0 = blockIdx.x * BT_;
    if (tid < BT_) {
        const int t = t0 + tid;
        if (t < T) {
            const int2 e2 = reinterpret_cast<const int2*>(tbe)[t];
            sei[tid] = e2.x;
            sek[tid] = e2.y;
            const float4 gij = g_geo[e2.x];
            const float4 gik = g_geo[e2.y];
            float cosv = gij.x * gik.x + gij.y * gik.y + gij.z * gik.z;
            cosv = fminf(fmaxf(cosv, -1.f), 1.f);
            #pragma unroll
            for (int j = 0; j < NB_; j++) {
                const float z = fmaf(gij.w, sA1[0][j],
                               fmaf(gik.w, sA1[1][j],
                               fmaf(cosv, sA1[2][j], sab1[j])));
                sH[j][tid] = silu_f(z);
            }
        } else {
            sei[tid] = -1;
            #pragma unroll
            for (int j = 0; j < NB_; j++) sH[j][tid] = 0.f;
        }
        if (t < T)
            asm volatile("red.global.add.u32 [%0], %1;"
                         :: "l"(&g_cnt[sei[tid]]), "r"(1) : "memory");
    }
    __syncthreads();

    // ---- phase 2: pre = H^T @ A2c + b1p, gather-add P/Q, silu, RED ----
    const int rg = tid >> 4;           // row group 0..15
    const int cg = tid & 15;           // col group 0..15
    const int row0 = rg * 8;
    const int col0 = cg * 8;

    // init accumulators with b1p
    u64 acc[8][4];
    {
        const float4 b_lo = *reinterpret_cast<const float4*>(&sb1p[col0]);
        const float4 b_hi = *reinterpret_cast<const float4*>(&sb1p[col0 + 4]);
        const u64 bb0 = pack2(b_lo.x, b_lo.y);
        const u64 bb1 = pack2(b_lo.z, b_lo.w);
        const u64 bb2 = pack2(b_hi.x, b_hi.y);
        const u64 bb3 = pack2(b_hi.z, b_hi.w);
        #pragma unroll
        for (int i = 0; i < 8; i++) {
            acc[i][0] = bb0; acc[i][1] = bb1; acc[i][2] = bb2; acc[i][3] = bb3;
        }
    }

    #pragma unroll
    for (int k = 0; k < NB_; k++) {
        float hr[8];
        *reinterpret_cast<float4*>(&hr[0]) = *reinterpret_cast<const float4*>(&sH[k][row0]);
        *reinterpret_cast<float4*>(&hr[4]) = *reinterpret_cast<const float4*>(&sH[k][row0 + 4]);
        const ulonglong2 w01 = *reinterpret_cast<const ulonglong2*>(&sA2c[k][col0]);
        const ulonglong2 w23 = *reinterpret_cast<const ulonglong2*>(&sA2c[k][col0 + 4]);
        #pragma unroll
        for (int i = 0; i < 8; i++) {
            const u64 hh = pack2(hr[i], hr[i]);
            ffma2(acc[i][0], hh, w01.x);
            ffma2(acc[i][1], hh, w01.y);
            ffma2(acc[i][2], hh, w23.x);
            ffma2(acc[i][3], hh, w23.y);
        }
    }

    #pragma unroll
    for (int i = 0; i < 8; i++) {
        const int r = row0 + i;
        const int eij = sei[r];
        if (eij < 0) continue;
        const int eik = sek[r];

        const float4 p0 = *reinterpret_cast<const float4*>(g_P + (size_t)eij * D_ + col0);
        const float4 p1 = *reinterpret_cast<const float4*>(g_P + (size_t)eij * D_ + col0 + 4);
        const float4 q0 = *reinterpret_cast<const float4*>(g_Q + (size_t)eik * D_ + col0);
        const float4 q1 = *reinterpret_cast<const float4*>(g_Q + (size_t)eik * D_ + col0 + 4);

        float c0, c1, c2, c3, c4, c5, c6, c7;
        unpack2(acc[i][0], c0, c1);
        unpack2(acc[i][1], c2, c3);
        unpack2(acc[i][2], c4, c5);
        unpack2(acc[i][3], c6, c7);

        const float m0 = silu_f(c0 + p0.x + q0.x);
        const float m1 = silu_f(c1 + p0.y + q0.y);
        const float m2 = silu_f(c2 + p0.z + q0.z);
        const float m3 = silu_f(c3 + p0.w + q0.w);
        const float m4 = silu_f(c4 + p1.x + q1.x);
        const float m5 = silu_f(c5 + p1.y + q1.y);
        const float m6 = silu_f(c6 + p1.z + q1.z);
        const float m7 = silu_f(c7 + p1.w + q1.w);

        float* dst = S + (size_t)eij * D_ + col0;
        asm volatile("red.global.add.v4.f32 [%0], {%1, %2, %3, %4};"
                     :: "l"(dst), "f"(m0), "f"(m1), "f"(m2), "f"(m3) : "memory");
        asm volatile("red.global.add.v4.f32 [%0], {%1, %2, %3, %4};"
                     :: "l"(dst + 4), "f"(m4), "f"(m5), "f"(m6), "f"(m7) : "memory");
    }
}

// ---------------- launch ----------------
extern "C" void kernel_launch(void* const* d_in, const int* in_sizes, int n_in,
                              void* d_out, int out_size) {
    const float* edge_attr = (const float*)d_in[0];
    // d_in[1] = three_body_indices (unused by the math)
    const int*   tbe       = (const int*)d_in[2];
    const float* ev        = (const float*)d_in[3];
    const float* A1        = (const float*)d_in[4];
    const float* ab1       = (const float*)d_in[5];
    const float* A2        = (const float*)d_in[6];
    const float* ab2       = (const float*)d_in[7];
    const float* W1        = (const float*)d_in[8];
    const float* b1        = (const float*)d_in[9];
    const float* W2        = (const float*)d_in[10];
    const float* b2        = (const float*)d_in[11];
    const float* Wu        = (const float*)d_in[12];
    const float* bu        = (const float*)d_in[13];
    float* out = (float*)d_out;

    const int E = in_sizes[0] / D_;
    const int T = in_sizes[2] / 2;

    void *pP, *pQ, *pcnt, *pWc, *pbcu;
    cudaGetSymbolAddress(&pP, g_P);
    cudaGetSymbolAddress(&pQ, g_Q);
    cudaGetSymbolAddress(&pcnt, g_cnt);
    cudaGetSymbolAddress(&pWc, g_Wc);
    cudaGetSymbolAddress(&pbcu, g_bcu);

    // S (segment sum of silu(pre)) lives in d_out; final GEMM is in-place.
    zero_kernel<<<1184, 256>>>(out, E);
    geo_kernel<<<(E + 255) / 256, 256>>>(ev, E);
    prep_kernel<<<128 + NB_ + 1, 128>>>(W2, Wu, b2, A2, W1, ab2, b1);

    const int gb = (E + 127) / 128;
    sgemm128<<<gb, 256>>>(edge_attr, W1, (float*)pP, E, nullptr, nullptr, nullptr);
    sgemm128<<<gb, 256>>>(edge_attr, W1 + 128 * 128, (float*)pQ, E, nullptr, nullptr, nullptr);

    const int tb = (T + BT_ - 1) / BT_;
    triplet_batch_kernel<<<tb, 256>>>(tbe, A1, ab1, out, T);

    sgemm128<<<gb, 256>>>(out, (const float*)pWc, out, E,
                          bu, (const int*)pcnt, (const float*)pbcu);
}